// round 16
// baseline (speedup 1.0000x reference)
#include <cuda_runtime.h>
#include <cuda_bf16.h>
#include <math.h>
#include <stdint.h>

// Problem constants
#define BATCH 2
#define SEQ   2048
#define EMBED 1024
#define HEADS 16
#define HDIM  64
#define MTOT  (BATCH*SEQ)     // 4096
#define BH    (BATCH*HEADS)   // 32
#define NW    (EMBED*EMBED)   // 1048576

// ---------------------------------------------------------------------------
// Scratch (device globals; no allocation allowed)
// ---------------------------------------------------------------------------
__device__ int8_t g_hq1[MTOT*EMBED],  g_hq0[MTOT*EMBED];    // hidden int8 hi/lo
__device__ int8_t g_wq1[4*NW],        g_wq0[4*NW];          // Wq,Wk,Wv,Wo int8
__device__ int8_t g_aq1[MTOT*EMBED],  g_aq0[MTOT*EMBED];    // attn-out int8
__device__ float  g_sh[MTOT], g_sw[4*EMBED], g_sat[MTOT];   // row scales
__device__ float  g_attnf[MTOT*EMBED];                       // attn out fp32
__device__ __nv_bfloat16 g_qh[BH*SEQ*HDIM],  g_ql[BH*SEQ*HDIM];   // [bh][s][dh] (pre-scaled)
__device__ __nv_bfloat16 g_kh[BH*SEQ*HDIM],  g_kl[BH*SEQ*HDIM];   // [bh][s][dh]
__device__ __nv_bfloat16 g_vth[BH*SEQ*HDIM], g_vtl[BH*SEQ*HDIM];  // [bh][dh][s]
__device__ int g_mflag[(SEQ/128)*(SEQ/64)];

// ---------------------------------------------------------------------------
// Helpers
// ---------------------------------------------------------------------------
__device__ __forceinline__ uint32_t pack_bf2(float lo_elem, float hi_elem) {
    uint32_t r;
    asm("cvt.rn.bf16x2.f32 %0, %1, %2;" : "=r"(r) : "f"(hi_elem), "f"(lo_elem));
    return r;
}
__device__ __forceinline__ void split_pack2(float x, float y, uint32_t& hi, uint32_t& lo) {
    float xh = __bfloat162float(__float2bfloat16_rn(x));
    float yh = __bfloat162float(__float2bfloat16_rn(y));
    hi = pack_bf2(xh, yh);
    lo = pack_bf2(x - xh, y - yh);
}
__device__ __forceinline__ void mma16816(float* c, const uint32_t* a, const uint32_t* b) {
    asm volatile(
        "mma.sync.aligned.m16n8k16.row.col.f32.bf16.bf16.f32 "
        "{%0,%1,%2,%3}, {%4,%5,%6,%7}, {%8,%9}, {%0,%1,%2,%3};"
        : "+f"(c[0]), "+f"(c[1]), "+f"(c[2]), "+f"(c[3])
        : "r"(a[0]), "r"(a[1]), "r"(a[2]), "r"(a[3]), "r"(b[0]), "r"(b[1]));
}
__device__ __forceinline__ void imma16832(int* c, const uint32_t* a, const uint32_t* b) {
    asm volatile(
        "mma.sync.aligned.m16n8k32.row.col.s32.s8.s8.s32 "
        "{%0,%1,%2,%3}, {%4,%5,%6,%7}, {%8,%9}, {%0,%1,%2,%3};"
        : "+r"(c[0]), "+r"(c[1]), "+r"(c[2]), "+r"(c[3])
        : "r"(a[0]), "r"(a[1]), "r"(a[2]), "r"(a[3]), "r"(b[0]), "r"(b[1]));
}
__device__ __forceinline__ uint32_t s2u(const void* p) {
    return (uint32_t)__cvta_generic_to_shared(p);
}
__device__ __forceinline__ void cpa16(uint32_t s, const void* g) {
    asm volatile("cp.async.cg.shared.global [%0], [%1], 16;" :: "r"(s), "l"(g));
}
__device__ __forceinline__ void cp_commit() { asm volatile("cp.async.commit_group;"); }
__device__ __forceinline__ void cp_wait0() { asm volatile("cp.async.wait_group 0;"); }
__device__ __forceinline__ void ldsm4(uint32_t* r, uint32_t a) {
    asm volatile("ldmatrix.sync.aligned.m8n8.x4.shared.b16 {%0,%1,%2,%3}, [%4];"
        : "=r"(r[0]), "=r"(r[1]), "=r"(r[2]), "=r"(r[3]) : "r"(a));
}
__device__ __forceinline__ float ex2(float x) {
    float r; asm("ex2.approx.f32 %0, %1;" : "=f"(r) : "f"(x)); return r;
}
__device__ __forceinline__ int8_t q8(float v) {
    int a = __float2int_rn(v);
    a = a > 127 ? 127 : (a < -127 ? -127 : a);
    return (int8_t)a;
}

// ---------------------------------------------------------------------------
// Row quantization: x ~= sc * (128*a1 + a0/2), per 1024-elem row.
// ---------------------------------------------------------------------------
__device__ __forceinline__
void quant_row(const float* __restrict__ src, int8_t* __restrict__ q1,
               int8_t* __restrict__ q0, float* __restrict__ sc)
{
    __shared__ float red[8];
    const int t = threadIdx.x;
    float4 v = ((const float4*)src)[t];
    float m = fmaxf(fmaxf(fabsf(v.x), fabsf(v.y)), fmaxf(fabsf(v.z), fabsf(v.w)));
#pragma unroll
    for (int d = 16; d; d >>= 1) m = fmaxf(m, __shfl_xor_sync(0xffffffffu, m, d));
    if ((t & 31) == 0) red[t >> 5] = m;
    __syncthreads();
    if (t == 0) {
        float x = red[0];
#pragma unroll
        for (int i = 1; i < 8; i++) x = fmaxf(x, red[i]);
        red[0] = fmaxf(x, 1e-20f);
    }
    __syncthreads();
    const float mm  = red[0];
    if (t == 0) *sc = mm * (1.0f / 16256.0f);
    const float inv = 16256.0f / mm;

    float a[4] = {v.x, v.y, v.z, v.w};
    char4 c1, c0;
    int8_t* p1 = (int8_t*)&c1; int8_t* p0 = (int8_t*)&c0;
#pragma unroll
    for (int j = 0; j < 4; j++) {
        float q = a[j] * inv;
        int hi = __float2int_rn(q * 0.0078125f);
        hi = hi > 127 ? 127 : (hi < -127 ? -127 : hi);
        float r = q - 128.0f * (float)hi;
        p1[j] = (int8_t)hi;
        p0[j] = q8(2.0f * r);
    }
    ((char4*)q1)[t] = c1;
    ((char4*)q0)[t] = c0;
}

// Inputs: rows 0..4095 hidden, then 1024 rows each of Wq,Wk,Wv,Wo
__global__ __launch_bounds__(256)
void quant_in_kernel(const float* __restrict__ hid,
                     const float* __restrict__ Wq, const float* __restrict__ Wk,
                     const float* __restrict__ Wv, const float* __restrict__ Wo)
{
    int row = blockIdx.x;
    if (row < MTOT) {
        size_t off = (size_t)row * EMBED;
        quant_row(hid + off, g_hq1 + off, g_hq0 + off, &g_sh[row]);
    } else {
        int wr = row - MTOT, wi = wr >> 10, lr = wr & 1023;
        const float* w = (wi == 0) ? Wq : (wi == 1) ? Wk : (wi == 2) ? Wv : Wo;
        size_t off = (size_t)wi * NW + (size_t)lr * EMBED;
        quant_row(w + (size_t)lr * EMBED, g_wq1 + off, g_wq0 + off, &g_sw[wi * EMBED + lr]);
    }
}

__global__ __launch_bounds__(256)
void quant_attn_kernel()
{
    int row = blockIdx.x;
    size_t off = (size_t)row * EMBED;
    quant_row(g_attnf + off, g_aq1 + off, g_aq0 + off, &g_sat[row]);
}

// ---------------------------------------------------------------------------
// Mask block flags
// ---------------------------------------------------------------------------
__global__ __launch_bounds__(256)
void mask_flags_kernel(const int* __restrict__ mask)
{
    const int* p = mask + (size_t)(blockIdx.y * 128) * SEQ + blockIdx.x * 64;
    int local = 0;
    for (int i = threadIdx.x; i < 128 * 16; i += 256) {
        int r = i >> 4, c4 = i & 15;
        int4 v = ((const int4*)(p + (size_t)r * SEQ))[c4];
        if (v.x == 0 || v.y == 0 || v.z == 0 || v.w == 0) local = 1;
    }
    int any = __syncthreads_or(local);
    if (threadIdx.x == 0) g_mflag[blockIdx.y * (SEQ/64) + blockIdx.x] = any;
}

// ---------------------------------------------------------------------------
// int8 GEMM: C[128,128] tile; A,B as (a1,a0) int8 pairs with row scales.
// val = sa*sb*(16384*S11 + 64*S01) + bias (a0b0/4 term dropped, ~2^-14).
// KT2=64 bytes/stage, 2-stage cp.async, ldmatrix-fed IMMA m16n8k32.
// MODE 0: fp32 row-major out. MODE 1: bf16 hi/lo head-split out.
// ---------------------------------------------------------------------------
#define STR2   80                     // bytes/row in smem (conflict-free)
#define IARR   (128*STR2)             // 10240 B per array
#define ISTAGE (4*IARR)               // 40960 B
#define ISMEM  (2*ISTAGE)             // 81920 B
#define KT2    64

template<int MODE>
__device__ __forceinline__
void igemm_body(const int8_t* __restrict__ A1, const int8_t* __restrict__ A0,
                const int8_t* __restrict__ B1, const int8_t* __restrict__ B0,
                const float* __restrict__ sa, const float* __restrict__ sb,
                const float* __restrict__ bias,
                float* __restrict__ outF,
                __nv_bfloat16* __restrict__ outH, __nv_bfloat16* __restrict__ outL,
                int trans, float osc)
{
    extern __shared__ __nv_bfloat16 dsm[];
    const uint32_t sbse = s2u(dsm);
    const int t = threadIdx.x, lane = t & 31, w = t >> 5;
    const int g = lane >> 2, tg = lane & 3;
    const int wm = w >> 2, wn = w & 3;
    const int m0 = blockIdx.y * 128, n0 = blockIdx.x * 128;

    // staging: row t>>1, bytes (t&1)*32..+32 per array
    const int lr = t >> 1, lc = (t & 1) * 32;
    const int8_t* gp[4] = {
        A1 + (size_t)(m0 + lr) * EMBED + lc,
        A0 + (size_t)(m0 + lr) * EMBED + lc,
        B1 + (size_t)(n0 + lr) * EMBED + lc,
        B0 + (size_t)(n0 + lr) * EMBED + lc };
    const uint32_t sp = sbse + lr * STR2 + lc;

    const uint32_t aoff = sbse + (wm * 64 + (lane & 15)) * STR2 + (lane >> 4) * 16;
    const uint32_t boff = sbse + 2 * IARR +
        (wn * 32 + (lane & 7) + (lane >> 4) * 8) * STR2 + ((lane >> 3) & 1) * 16;

    int acc1[4][4][4], acc01[4][4][4];
#pragma unroll
    for (int a = 0; a < 4; a++)
#pragma unroll
        for (int b = 0; b < 4; b++)
#pragma unroll
            for (int c = 0; c < 4; c++) { acc1[a][b][c] = 0; acc01[a][b][c] = 0; }

    // prologue: stage 0
#pragma unroll
    for (int a = 0; a < 4; a++) {
        cpa16(sp + a * IARR,      gp[a]);
        cpa16(sp + a * IARR + 16, gp[a] + 16);
    }
    cp_commit();

    const int NIT = EMBED / KT2;   // 16
    for (int kt = 0; kt < NIT; kt++) {
        const int st = kt & 1;
        cp_wait0();
        __syncthreads();
        if (kt + 1 < NIT) {
            uint32_t base = sp + (st ^ 1) * ISTAGE;
            int k0 = (kt + 1) * KT2;
#pragma unroll
            for (int a = 0; a < 4; a++) {
                cpa16(base + a * IARR,      gp[a] + k0);
                cpa16(base + a * IARR + 16, gp[a] + k0 + 16);
            }
            cp_commit();
        }

        const uint32_t stB = st * ISTAGE;
#pragma unroll
        for (int ks = 0; ks < 2; ks++) {
            const int kb = ks * 32;
            uint32_t a1f[4][4], a0f[4][4], b1f[2][4], b0f[2][4];
#pragma unroll
            for (int mf = 0; mf < 4; mf++) {
                uint32_t ad = aoff + stB + mf * 16 * STR2 + kb;
                ldsm4(a1f[mf], ad);
                ldsm4(a0f[mf], ad + IARR);
            }
#pragma unroll
            for (int np = 0; np < 2; np++) {
                uint32_t bd = boff + stB + np * 16 * STR2 + kb;
                ldsm4(b1f[np], bd);
                ldsm4(b0f[np], bd + IARR);
            }
#pragma unroll
            for (int mf = 0; mf < 4; mf++)
#pragma unroll
                for (int nf = 0; nf < 4; nf++)
                    imma16832(acc1[mf][nf],  a1f[mf], &b1f[nf >> 1][(nf & 1) * 2]);
#pragma unroll
            for (int mf = 0; mf < 4; mf++)
#pragma unroll
                for (int nf = 0; nf < 4; nf++)
                    imma16832(acc01[mf][nf], a1f[mf], &b0f[nf >> 1][(nf & 1) * 2]);
#pragma unroll
            for (int mf = 0; mf < 4; mf++)
#pragma unroll
                for (int nf = 0; nf < 4; nf++)
                    imma16832(acc01[mf][nf], a0f[mf], &b1f[nf >> 1][(nf & 1) * 2]);
        }
    }

    // Epilogue
#pragma unroll
    for (int mf = 0; mf < 4; mf++)
#pragma unroll
        for (int nf = 0; nf < 4; nf++) {
            int r0 = m0 + wm * 64 + mf * 16 + g;
            int c0 = n0 + wn * 32 + nf * 8 + 2 * tg;
#pragma unroll
            for (int e = 0; e < 4; e++) {
                int r = r0 + ((e >= 2) ? 8 : 0);
                int c = c0 + (e & 1);
                float dot = (16384.0f * (float)acc1[mf][nf][e] +
                             64.0f    * (float)acc01[mf][nf][e]) * sa[r] * sb[c];
                float val = (dot + bias[c]) * osc;
                if (MODE == 0) {
                    outF[(size_t)r * EMBED + c] = val;
                } else {
                    int b  = r >> 11;
                    int s  = r & (SEQ - 1);
                    int h  = c >> 6;
                    int dh = c & (HDIM - 1);
                    size_t idx = trans
                        ? (((size_t)(b * HEADS + h)) * HDIM + dh) * SEQ + s
                        : (((size_t)(b * HEADS + h)) * SEQ + s) * HDIM + dh;
                    __nv_bfloat16 hv = __float2bfloat16_rn(val);
                    outH[idx] = hv;
                    outL[idx] = __float2bfloat16_rn(val - __bfloat162float(hv));
                }
            }
        }
}

// Q gets pre-scaled by 0.125*log2(e) so attention works in the exp2 domain.
#define QSCALE 0.18033688011112042f   // log2(e)/8

__global__ __launch_bounds__(256)
void qkv_kernel(const float* __restrict__ bq, const float* __restrict__ bk,
                const float* __restrict__ bv)
{
    int z = blockIdx.z;
    const int8_t* B1 = g_wq1 + (size_t)z * NW;
    const int8_t* B0 = g_wq0 + (size_t)z * NW;
    const float*  sb = g_sw + z * EMBED;
    if (z == 0)
        igemm_body<1>(g_hq1, g_hq0, B1, B0, g_sh, sb, bq, nullptr, g_qh, g_ql, 0, QSCALE);
    else if (z == 1)
        igemm_body<1>(g_hq1, g_hq0, B1, B0, g_sh, sb, bk, nullptr, g_kh, g_kl, 0, 1.0f);
    else
        igemm_body<1>(g_hq1, g_hq0, B1, B0, g_sh, sb, bv, nullptr, g_vth, g_vtl, 1, 1.0f);
}

__global__ __launch_bounds__(256)
void oproj_kernel(const float* __restrict__ bo, float* __restrict__ out)
{
    igemm_body<0>(g_aq1, g_aq0, g_wq1 + 3*(size_t)NW, g_wq0 + 3*(size_t)NW,
                  g_sat, g_sw + 3*EMBED, bo, out, nullptr, nullptr, 0, 1.0f);
}

// ---------------------------------------------------------------------------
// Flash attention (R13 best variant, unchanged except fp32 output).
// ---------------------------------------------------------------------------
#define KSTR   72
#define AARR   (64*KSTR*2)
#define ASTAGE (4*AARR)
#define ASMEM  (2*ASTAGE)             // 73728 B

__global__ __launch_bounds__(256)
void attn_mma(const __nv_bfloat16* __restrict__ qh_, const __nv_bfloat16* __restrict__ ql_,
              const __nv_bfloat16* __restrict__ kh_, const __nv_bfloat16* __restrict__ kl_,
              const __nv_bfloat16* __restrict__ vth_, const __nv_bfloat16* __restrict__ vtl_,
              const int* __restrict__ mask,
              float* __restrict__ outF)
{
    extern __shared__ __nv_bfloat16 dsm[];
    const uint32_t sb = s2u(dsm);
    const int t = threadIdx.x, lane = t & 31, w = t >> 5;
    const int g = lane >> 2, tg = lane & 3;
    const int bh = blockIdx.y;
    const int q0 = blockIdx.x * 128;
    const size_t base = (size_t)bh * SEQ * HDIM;

    const int lr = t >> 2, lcb = (t & 3) * 16;
    const __nv_bfloat16* gp[4] = {
        kh_  + base + (size_t)lr * HDIM + lcb,
        kl_  + base + (size_t)lr * HDIM + lcb,
        vth_ + base + (size_t)lr * SEQ  + lcb,
        vtl_ + base + (size_t)lr * SEQ  + lcb };
    const uint32_t sp = sb + (lr * KSTR + lcb) * 2;

    const uint32_t foff = sb +
        ((((lane & 7) + (lane >> 4) * 8) * KSTR + ((lane >> 3) & 1) * 8) * 2);

    {
#pragma unroll
        for (int a = 0; a < 4; a++) {
            cpa16(sp + a * AARR,      gp[a]);
            cpa16(sp + a * AARR + 16, gp[a] + 8);
        }
        cp_commit();
    }

    const int r0 = q0 + w * 16 + g;
    uint32_t qfh[4][4], qfl[4][4];
#pragma unroll
    for (int kf = 0; kf < 4; kf++) {
        size_t i0 = base + (size_t)r0 * HDIM + kf * 16 + 2 * tg;
        size_t i1 = base + (size_t)(r0 + 8) * HDIM + kf * 16 + 2 * tg;
        qfh[kf][0] = *(const uint32_t*)&qh_[i0];
        qfh[kf][1] = *(const uint32_t*)&qh_[i1];
        qfh[kf][2] = *(const uint32_t*)&qh_[i0 + 8];
        qfh[kf][3] = *(const uint32_t*)&qh_[i1 + 8];
        qfl[kf][0] = *(const uint32_t*)&ql_[i0];
        qfl[kf][1] = *(const uint32_t*)&ql_[i1];
        qfl[kf][2] = *(const uint32_t*)&ql_[i0 + 8];
        qfl[kf][3] = *(const uint32_t*)&ql_[i1 + 8];
    }

    float o[8][4];
#pragma unroll
    for (int nf = 0; nf < 8; nf++)
#pragma unroll
        for (int e = 0; e < 4; e++) o[nf][e] = 0.f;
    float m1 = -INFINITY, m2 = -INFINITY, l1 = 0.f, l2 = 0.f;

    const int NIT = SEQ / 64;

    for (int it = 0; it < NIT; it++) {
        const int st = it & 1;
        cp_wait0();
        __syncthreads();
        if (it + 1 < NIT) {
            const int k0n = (it + 1) * 64;
            uint32_t dstb = sp + (st ^ 1) * ASTAGE;
            cpa16(dstb,               gp[0] + (size_t)k0n * HDIM);
            cpa16(dstb + 16,          gp[0] + (size_t)k0n * HDIM + 8);
            cpa16(dstb + AARR,        gp[1] + (size_t)k0n * HDIM);
            cpa16(dstb + AARR + 16,   gp[1] + (size_t)k0n * HDIM + 8);
            cpa16(dstb + 2*AARR,      gp[2] + k0n);
            cpa16(dstb + 2*AARR + 16, gp[2] + k0n + 8);
            cpa16(dstb + 3*AARR,      gp[3] + k0n);
            cpa16(dstb + 3*AARR + 16, gp[3] + k0n + 8);
            cp_commit();
        }

        const uint32_t stB = st * ASTAGE;
        const int k0 = it * 64;

        float s[8][4];
#pragma unroll
        for (int nf = 0; nf < 8; nf++)
#pragma unroll
            for (int e = 0; e < 4; e++) s[nf][e] = 0.f;

#pragma unroll
        for (int kf = 0; kf < 4; kf++) {
            uint32_t kh4[4][4], kl4[4][4];
#pragma unroll
            for (int np = 0; np < 4; np++) {
                uint32_t ad = foff + stB + (np * 16 * KSTR + kf * 16) * 2;
                ldsm4(kh4[np], ad);
                ldsm4(kl4[np], ad + AARR);
            }
#pragma unroll
            for (int nf = 0; nf < 8; nf++)
                mma16816(s[nf], qfh[kf], &kh4[nf >> 1][(nf & 1) * 2]);
#pragma unroll
            for (int nf = 0; nf < 8; nf++)
                mma16816(s[nf], qfh[kf], &kl4[nf >> 1][(nf & 1) * 2]);
#pragma unroll
            for (int nf = 0; nf < 8; nf++)
                mma16816(s[nf], qfl[kf], &kh4[nf >> 1][(nf & 1) * 2]);
        }

        const int mflag = g_mflag[(q0 >> 7) * (SEQ/64) + (k0 >> 6)];
        if (mflag) {
#pragma unroll
            for (int nf = 0; nf < 8; nf++) {
                int kc = k0 + nf * 8 + 2 * tg;
                int2 mv0 = *(const int2*)&mask[(size_t)r0 * SEQ + kc];
                int2 mv1 = *(const int2*)&mask[(size_t)(r0 + 8) * SEQ + kc];
                if (!mv0.x) s[nf][0] = -1e9f;
                if (!mv0.y) s[nf][1] = -1e9f;
                if (!mv1.x) s[nf][2] = -1e9f;
                if (!mv1.y) s[nf][3] = -1e9f;
            }
        }

        float mt1 = -INFINITY, mt2 = -INFINITY;
#pragma unroll
        for (int nf = 0; nf < 8; nf++) {
            mt1 = fmaxf(mt1, fmaxf(s[nf][0], s[nf][1]));
            mt2 = fmaxf(mt2, fmaxf(s[nf][2], s[nf][3]));
        }
        mt1 = fmaxf(mt1, __shfl_xor_sync(0xffffffffu, mt1, 1));
        mt1 = fmaxf(mt1, __shfl_xor_sync(0xffffffffu, mt1, 2));
        mt2 = fmaxf(mt2, __shfl_xor_sync(0xffffffffu, mt2, 1));
        mt2 = fmaxf(mt2, __shfl_xor_sync(0xffffffffu, mt2, 2));
        float m1n = fmaxf(m1, mt1), m2n = fmaxf(m2, mt2);
        float a1 = ex2(m1 - m1n), a2 = ex2(m2 - m2n);

#pragma unroll
        for (int nf = 0; nf < 8; nf++) {
            o[nf][0] *= a1; o[nf][1] *= a1;
            o[nf][2] *= a2; o[nf][3] *= a2;
        }

        float sum1 = 0.f, sum2 = 0.f;
#pragma unroll
        for (int kf = 0; kf < 4; kf++) {
            float e00 = ex2(s[2*kf][0]   - m1n), e01 = ex2(s[2*kf][1]   - m1n);
            float e02 = ex2(s[2*kf][2]   - m2n), e03 = ex2(s[2*kf][3]   - m2n);
            float e10 = ex2(s[2*kf+1][0] - m1n), e11 = ex2(s[2*kf+1][1] - m1n);
            float e12 = ex2(s[2*kf+1][2] - m2n), e13 = ex2(s[2*kf+1][3] - m2n);
            sum1 += e00 + e01 + e10 + e11;
            sum2 += e02 + e03 + e12 + e13;

            uint32_t pH[4], pL[4];
            split_pack2(e00, e01, pH[0], pL[0]);
            split_pack2(e02, e03, pH[1], pL[1]);
            split_pack2(e10, e11, pH[2], pL[2]);
            split_pack2(e12, e13, pH[3], pL[3]);

            uint32_t vh4[4][4], vl4[4][4];
#pragma unroll
            for (int np = 0; np < 4; np++) {
                uint32_t ad = foff + stB + 2*AARR + (np * 16 * KSTR + kf * 16) * 2;
                ldsm4(vh4[np], ad);
                ldsm4(vl4[np], ad + AARR);
            }
#pragma unroll
            for (int nf = 0; nf < 8; nf++)
                mma16816(o[nf], pH, &vh4[nf >> 1][(nf & 1) * 2]);
#pragma unroll
            for (int nf = 0; nf < 8; nf++)
                mma16816(o[nf], pH, &vl4[nf >> 1][(nf & 1) * 2]);
#pragma unroll
            for (int nf = 0; nf < 8; nf++)
                mma16816(o[nf], pL, &vh4[nf >> 1][(nf & 1) * 2]);
        }

        sum1 += __shfl_xor_sync(0xffffffffu, sum1, 1);
        sum1 += __shfl_xor_sync(0xffffffffu, sum1, 2);
        sum2 += __shfl_xor_sync(0xffffffffu, sum2, 1);
        sum2 += __shfl_xor_sync(0xffffffffu, sum2, 2);
        l1 = l1 * a1 + sum1;
        l2 = l2 * a2 + sum2;
        m1 = m1n; m2 = m2n;
    }

    // epilogue: fp32 attn out [b][s][D]
    const float inv1 = 1.f / l1, inv2 = 1.f / l2;
    const int b = bh / HEADS, h = bh % HEADS;
#pragma unroll
    for (int nf = 0; nf < 8; nf++) {
        int col = h * HDIM + nf * 8 + 2 * tg;
        size_t i0 = ((size_t)(b * SEQ + r0)) * EMBED + col;
        size_t i1 = ((size_t)(b * SEQ + r0 + 8)) * EMBED + col;
        *(float2*)&outF[i0] = make_float2(o[nf][0] * inv1, o[nf][1] * inv1);
        *(float2*)&outF[i1] = make_float2(o[nf][2] * inv2, o[nf][3] * inv2);
    }
}

// ---------------------------------------------------------------------------
extern "C" void kernel_launch(void* const* d_in, const int* in_sizes, int n_in,
                              void* d_out, int out_size)
{
    const float* hidden = (const float*)d_in[0];
    const int*   mask   = (const int*)  d_in[1];
    const float* Wq     = (const float*)d_in[2];
    const float* bq     = (const float*)d_in[3];
    const float* Wk     = (const float*)d_in[4];
    const float* bk     = (const float*)d_in[5];
    const float* Wv     = (const float*)d_in[6];
    const float* bv     = (const float*)d_in[7];
    const float* Wo     = (const float*)d_in[8];
    const float* bo     = (const float*)d_in[9];
    float* out = (float*)d_out;

    __nv_bfloat16 *qh, *ql, *kh, *kl, *vth, *vtl;
    float* attnf;
    cudaGetSymbolAddress((void**)&qh,    g_qh);  cudaGetSymbolAddress((void**)&ql,  g_ql);
    cudaGetSymbolAddress((void**)&kh,    g_kh);  cudaGetSymbolAddress((void**)&kl,  g_kl);
    cudaGetSymbolAddress((void**)&vth,   g_vth); cudaGetSymbolAddress((void**)&vtl, g_vtl);
    cudaGetSymbolAddress((void**)&attnf, g_attnf);

    static bool attr_set = false;
    if (!attr_set) {
        cudaFuncSetAttribute(qkv_kernel,   cudaFuncAttributeMaxDynamicSharedMemorySize, ISMEM);
        cudaFuncSetAttribute(oproj_kernel, cudaFuncAttributeMaxDynamicSharedMemorySize, ISMEM);
        cudaFuncSetAttribute(attn_mma,     cudaFuncAttributeMaxDynamicSharedMemorySize, ASMEM);
        attr_set = true;
    }

    // Quantize hidden + weights; mask flags
    quant_in_kernel<<<MTOT + 4 * EMBED, 256>>>(hidden, Wq, Wk, Wv, Wo);
    mask_flags_kernel<<<dim3(SEQ/64, SEQ/128), 256>>>(mask);

    // QKV projections (int8 IMMA, grid.z = 3)
    dim3 gq(EMBED / 128, MTOT / 128, 3);   // (8, 32, 3)
    qkv_kernel<<<gq, 256, ISMEM>>>(bq, bk, bv);

    // Attention (bf16x3 HMMA, fp32 out)
    dim3 ag(SEQ / 128, BH);                // (16, 32)
    attn_mma<<<ag, 256, ASMEM>>>(qh, ql, kh, kl, vth, vtl, mask, attnf);

    // Quantize attention output, then O projection (int8 IMMA)
    quant_attn_kernel<<<MTOT, 256>>>();
    dim3 go(EMBED / 128, MTOT / 128);      // (8, 32)
    oproj_kernel<<<go, 256, ISMEM>>>(bo, out);
}

// round 17
// speedup vs baseline: 1.7623x; 1.7623x over previous
#include <cuda_runtime.h>
#include <cuda_bf16.h>
#include <math.h>
#include <stdint.h>

// Problem constants
#define BATCH 2
#define SEQ   2048
#define EMBED 1024
#define HEADS 16
#define HDIM  64
#define MTOT  (BATCH*SEQ)     // 4096
#define BH    (BATCH*HEADS)   // 32

// ---------------------------------------------------------------------------
// Scratch (device globals; no allocation allowed)
// ---------------------------------------------------------------------------
__device__ __nv_bfloat16 g_hh[MTOT*EMBED],  g_hl[MTOT*EMBED];
__device__ __nv_bfloat16 g_wqh[EMBED*EMBED], g_wql[EMBED*EMBED];
__device__ __nv_bfloat16 g_wkh[EMBED*EMBED], g_wkl[EMBED*EMBED];
__device__ __nv_bfloat16 g_wvh[EMBED*EMBED], g_wvl[EMBED*EMBED];
__device__ __nv_bfloat16 g_woh[EMBED*EMBED], g_wol[EMBED*EMBED];
__device__ __nv_bfloat16 g_qh[BH*SEQ*HDIM],  g_ql[BH*SEQ*HDIM];   // [bh][s][dh] (pre-scaled)
__device__ __nv_bfloat16 g_kh[BH*SEQ*HDIM],  g_kl[BH*SEQ*HDIM];   // [bh][s][dh]
__device__ __nv_bfloat16 g_vth[BH*SEQ*HDIM], g_vtl[BH*SEQ*HDIM];  // [bh][dh][s]
__device__ float         g_attnf[MTOT*EMBED];                      // attn out fp32
__device__ __nv_bfloat16 g_ah[MTOT*EMBED],   g_al[MTOT*EMBED];    // attn out split
__device__ int g_mflag[(SEQ/128)*(SEQ/64)];                        // [16][32]

// ---------------------------------------------------------------------------
// Helpers
// ---------------------------------------------------------------------------
__device__ __forceinline__ uint32_t pack_bf2(float lo_elem, float hi_elem) {
    uint32_t r;
    asm("cvt.rn.bf16x2.f32 %0, %1, %2;" : "=r"(r) : "f"(hi_elem), "f"(lo_elem));
    return r;
}
__device__ __forceinline__ void split_pack2(float x, float y, uint32_t& hi, uint32_t& lo) {
    float xh = __bfloat162float(__float2bfloat16_rn(x));
    float yh = __bfloat162float(__float2bfloat16_rn(y));
    hi = pack_bf2(xh, yh);
    lo = pack_bf2(x - xh, y - yh);
}
__device__ __forceinline__ void mma16816(float* c, const uint32_t* a, const uint32_t* b) {
    asm volatile(
        "mma.sync.aligned.m16n8k16.row.col.f32.bf16.bf16.f32 "
        "{%0,%1,%2,%3}, {%4,%5,%6,%7}, {%8,%9}, {%0,%1,%2,%3};"
        : "+f"(c[0]), "+f"(c[1]), "+f"(c[2]), "+f"(c[3])
        : "r"(a[0]), "r"(a[1]), "r"(a[2]), "r"(a[3]), "r"(b[0]), "r"(b[1]));
}
__device__ __forceinline__ uint32_t s2u(const void* p) {
    return (uint32_t)__cvta_generic_to_shared(p);
}
__device__ __forceinline__ void cpa16(uint32_t s, const void* g) {
    asm volatile("cp.async.cg.shared.global [%0], [%1], 16;" :: "r"(s), "l"(g));
}
__device__ __forceinline__ void cp_commit() { asm volatile("cp.async.commit_group;"); }
__device__ __forceinline__ void cp_wait0() { asm volatile("cp.async.wait_group 0;"); }
__device__ __forceinline__ void ldsm4(uint32_t* r, uint32_t a) {
    asm volatile("ldmatrix.sync.aligned.m8n8.x4.shared.b16 {%0,%1,%2,%3}, [%4];"
        : "=r"(r[0]), "=r"(r[1]), "=r"(r[2]), "=r"(r[3]) : "r"(a));
}
__device__ __forceinline__ float ex2(float x) {
    float r; asm("ex2.approx.f32 %0, %1;" : "=f"(r) : "f"(x)); return r;
}

// ---------------------------------------------------------------------------
// Fused split: hidden + 4 weight matrices in one launch.
// ---------------------------------------------------------------------------
#define NH (MTOT*EMBED)     // 4194304
#define NW (EMBED*EMBED)    // 1048576

__global__ __launch_bounds__(256)
void split_all_kernel(const float* __restrict__ hid,
                      const float* __restrict__ Wq, const float* __restrict__ Wk,
                      const float* __restrict__ Wv, const float* __restrict__ Wo)
{
    size_t i = ((size_t)blockIdx.x * 256 + threadIdx.x) * 8;
    const float* src; __nv_bfloat16 *h, *l; size_t off;
    if (i < NH)               { src = hid; h = g_hh;  l = g_hl;  off = i; }
    else if (i < NH + NW)     { src = Wq;  h = g_wqh; l = g_wql; off = i - NH; }
    else if (i < NH + 2*NW)   { src = Wk;  h = g_wkh; l = g_wkl; off = i - NH - NW; }
    else if (i < NH + 3*NW)   { src = Wv;  h = g_wvh; l = g_wvl; off = i - NH - 2*(size_t)NW; }
    else                      { src = Wo;  h = g_woh; l = g_wol; off = i - NH - 3*(size_t)NW; }
    float4 v0 = *(const float4*)(src + off);
    float4 v1 = *(const float4*)(src + off + 4);
    float a[8] = {v0.x, v0.y, v0.z, v0.w, v1.x, v1.y, v1.z, v1.w};
    uint32_t hp[4], lp[4];
#pragma unroll
    for (int j = 0; j < 4; j++) split_pack2(a[2*j], a[2*j+1], hp[j], lp[j]);
    *(uint4*)(h + off) = make_uint4(hp[0], hp[1], hp[2], hp[3]);
    *(uint4*)(l + off) = make_uint4(lp[0], lp[1], lp[2], lp[3]);
}

// Split the fp32 attention output into bf16 hi/lo for the O projection.
__global__ __launch_bounds__(256)
void split_attn_kernel()
{
    size_t i = ((size_t)blockIdx.x * 256 + threadIdx.x) * 8;
    float4 v0 = *(const float4*)(g_attnf + i);
    float4 v1 = *(const float4*)(g_attnf + i + 4);
    float a[8] = {v0.x, v0.y, v0.z, v0.w, v1.x, v1.y, v1.z, v1.w};
    uint32_t hp[4], lp[4];
#pragma unroll
    for (int j = 0; j < 4; j++) split_pack2(a[2*j], a[2*j+1], hp[j], lp[j]);
    *(uint4*)(g_ah + i) = make_uint4(hp[0], hp[1], hp[2], hp[3]);
    *(uint4*)(g_al + i) = make_uint4(lp[0], lp[1], lp[2], lp[3]);
}

// ---------------------------------------------------------------------------
// Mask block flags: flag[qb][kb] = any zero in mask[qb*128.., kb*64..]
// ---------------------------------------------------------------------------
__global__ __launch_bounds__(256)
void mask_flags_kernel(const int* __restrict__ mask)
{
    const int* p = mask + (size_t)(blockIdx.y * 128) * SEQ + blockIdx.x * 64;
    int local = 0;
    for (int i = threadIdx.x; i < 128 * 16; i += 256) {
        int r = i >> 4, c4 = i & 15;
        int4 v = ((const int4*)(p + (size_t)r * SEQ))[c4];
        if (v.x == 0 || v.y == 0 || v.z == 0 || v.w == 0) local = 1;
    }
    int any = __syncthreads_or(local);
    if (threadIdx.x == 0) g_mflag[blockIdx.y * (SEQ/64) + blockIdx.x] = any;
}

// ---------------------------------------------------------------------------
// bf16x3 GEMM core (R10 config): KT=16, 2-stage cp.async, ldmatrix-fed,
// 2 CTAs/SM, one barrier per iteration.
// ---------------------------------------------------------------------------
#define KT    16
#define SSTR  24                      // halves; 48B row stride (conflict-free LDSM)
#define GARR  (128*SSTR*2)            // 6144 B per array
#define GSTAGE (4*GARR)               // 24576 B
#define GSMEM  (2*GSTAGE)             // 49152 B

template<int MODE>
__device__ __forceinline__
void gemm_body(const __nv_bfloat16* __restrict__ Ah, const __nv_bfloat16* __restrict__ Al,
               const __nv_bfloat16* __restrict__ Bh, const __nv_bfloat16* __restrict__ Bl,
               const float* __restrict__ bias,
               float* __restrict__ outF,
               __nv_bfloat16* __restrict__ outH, __nv_bfloat16* __restrict__ outL,
               int trans, float osc)
{
    extern __shared__ __nv_bfloat16 dsm[];
    const uint32_t sb = s2u(dsm);
    const int K = EMBED;
    const int t = threadIdx.x, lane = t & 31, w = t >> 5;
    const int g = lane >> 2, tg = lane & 3;
    const int wm = w >> 2, wn = w & 3;
    const int m0 = blockIdx.y * 128, n0 = blockIdx.x * 128;

    const int lr = t >> 1, lc = (t & 1) * 8;
    const __nv_bfloat16* gp[4] = {
        Ah + (size_t)(m0 + lr) * K + lc,
        Al + (size_t)(m0 + lr) * K + lc,
        Bh + (size_t)(n0 + lr) * K + lc,
        Bl + (size_t)(n0 + lr) * K + lc };
    const uint32_t sp = sb + (lr * SSTR + lc) * 2;

    const uint32_t aoff = sb + ((wm * 64 + (lane & 15)) * SSTR + (lane >> 4) * 8) * 2;
    const uint32_t boff = sb + 2 * GARR +
        (((wn * 32 + (lane & 7) + (lane >> 4) * 8) * SSTR + ((lane >> 3) & 1) * 8) * 2);

    float acc[4][4][4];
#pragma unroll
    for (int a = 0; a < 4; a++)
#pragma unroll
        for (int b = 0; b < 4; b++)
#pragma unroll
            for (int c = 0; c < 4; c++) acc[a][b][c] = 0.f;

    // prologue: tile 0
#pragma unroll
    for (int a = 0; a < 4; a++) cpa16(sp + a * GARR, gp[a]);
    cp_commit();

    const int NKT = K / KT;   // 64
    for (int kt = 0; kt < NKT; kt++) {
        const int st = kt & 1;
        cp_wait0();
        __syncthreads();
        if (kt + 1 < NKT) {
            uint32_t base = sp + (st ^ 1) * GSTAGE;
            int k0 = (kt + 1) * KT;
#pragma unroll
            for (int a = 0; a < 4; a++) cpa16(base + a * GARR, gp[a] + k0);
            cp_commit();
        }

        const uint32_t stB = st * GSTAGE;
        uint32_t aH[4][4], aL[4][4], bHf[2][4], bLf[2][4];
#pragma unroll
        for (int mf = 0; mf < 4; mf++) {
            uint32_t ad = aoff + stB + (mf * 16 * SSTR) * 2;
            ldsm4(aH[mf], ad);
            ldsm4(aL[mf], ad + GARR);
        }
#pragma unroll
        for (int np = 0; np < 2; np++) {
            uint32_t bd = boff + stB + (np * 16 * SSTR) * 2;
            ldsm4(bHf[np], bd);
            ldsm4(bLf[np], bd + GARR);
        }
#pragma unroll
        for (int mf = 0; mf < 4; mf++)
#pragma unroll
            for (int nf = 0; nf < 4; nf++)
                mma16816(acc[mf][nf], aH[mf], &bHf[nf >> 1][(nf & 1) * 2]);
#pragma unroll
        for (int mf = 0; mf < 4; mf++)
#pragma unroll
            for (int nf = 0; nf < 4; nf++)
                mma16816(acc[mf][nf], aH[mf], &bLf[nf >> 1][(nf & 1) * 2]);
#pragma unroll
        for (int mf = 0; mf < 4; mf++)
#pragma unroll
            for (int nf = 0; nf < 4; nf++)
                mma16816(acc[mf][nf], aL[mf], &bHf[nf >> 1][(nf & 1) * 2]);
    }

    // Epilogue
#pragma unroll
    for (int mf = 0; mf < 4; mf++)
#pragma unroll
        for (int nf = 0; nf < 4; nf++) {
            int r0 = m0 + wm * 64 + mf * 16 + g;
            int c0 = n0 + wn * 32 + nf * 8 + 2 * tg;
#pragma unroll
            for (int e = 0; e < 4; e++) {
                int r = r0 + ((e >= 2) ? 8 : 0);
                int c = c0 + (e & 1);
                float val = (acc[mf][nf][e] + bias[c]) * osc;
                if (MODE == 0) {
                    outF[(size_t)r * EMBED + c] = val;
                } else {
                    int b  = r >> 11;
                    int s  = r & (SEQ - 1);
                    int h  = c >> 6;
                    int dh = c & (HDIM - 1);
                    size_t idx = trans
                        ? (((size_t)(b * HEADS + h)) * HDIM + dh) * SEQ + s
                        : (((size_t)(b * HEADS + h)) * SEQ + s) * HDIM + dh;
                    __nv_bfloat16 hv = __float2bfloat16_rn(val);
                    outH[idx] = hv;
                    outL[idx] = __float2bfloat16_rn(val - __bfloat162float(hv));
                }
            }
        }
}

// Q gets pre-scaled by 0.125*log2(e) so attention works in the exp2 domain.
#define QSCALE 0.18033688011112042f   // log2(e)/8

// Fused QKV: grid.z selects projection (0=Q, 1=K, 2=V-transposed)
__global__ __launch_bounds__(256, 2)
void qkv_kernel(const __nv_bfloat16* __restrict__ hh, const __nv_bfloat16* __restrict__ hl,
                const float* __restrict__ bq, const float* __restrict__ bk,
                const float* __restrict__ bv)
{
    int z = blockIdx.z;
    if (z == 0)
        gemm_body<1>(hh, hl, g_wqh, g_wql, bq, nullptr, g_qh, g_ql, 0, QSCALE);
    else if (z == 1)
        gemm_body<1>(hh, hl, g_wkh, g_wkl, bk, nullptr, g_kh, g_kl, 0, 1.0f);
    else
        gemm_body<1>(hh, hl, g_wvh, g_wvl, bv, nullptr, g_vth, g_vtl, 1, 1.0f);
}

// O projection: fp32 out
__global__ __launch_bounds__(256, 2)
void oproj_kernel(const float* __restrict__ bo, float* __restrict__ out)
{
    gemm_body<0>(g_ah, g_al, g_woh, g_wol, bo, out, nullptr, nullptr, 0, 1.0f);
}

// ---------------------------------------------------------------------------
// Flash attention (R13 fused-softmax variant) with fp32 output epilogue
// (measured -16us vs bf16-split epilogue in R16).
// ---------------------------------------------------------------------------
#define KSTR   72                     // halves; 144B row stride (conflict-free)
#define AARR   (64*KSTR*2)            // 9216 B per array
#define ASTAGE (4*AARR)               // 36864 B
#define ASMEM  (2*ASTAGE)             // 73728 B

__global__ __launch_bounds__(256)
void attn_mma(const __nv_bfloat16* __restrict__ qh_, const __nv_bfloat16* __restrict__ ql_,
              const __nv_bfloat16* __restrict__ kh_, const __nv_bfloat16* __restrict__ kl_,
              const __nv_bfloat16* __restrict__ vth_, const __nv_bfloat16* __restrict__ vtl_,
              const int* __restrict__ mask,
              float* __restrict__ outF)
{
    extern __shared__ __nv_bfloat16 dsm[];
    const uint32_t sb = s2u(dsm);
    const int t = threadIdx.x, lane = t & 31, w = t >> 5;
    const int g = lane >> 2, tg = lane & 3;
    const int bh = blockIdx.y;
    const int q0 = blockIdx.x * 128;
    const size_t base = (size_t)bh * SEQ * HDIM;

    const int lr = t >> 2, lcb = (t & 3) * 16;
    const __nv_bfloat16* gp[4] = {
        kh_  + base + (size_t)lr * HDIM + lcb,
        kl_  + base + (size_t)lr * HDIM + lcb,
        vth_ + base + (size_t)lr * SEQ  + lcb,
        vtl_ + base + (size_t)lr * SEQ  + lcb };
    const uint32_t sp = sb + (lr * KSTR + lcb) * 2;

    const uint32_t foff = sb +
        ((((lane & 7) + (lane >> 4) * 8) * KSTR + ((lane >> 3) & 1) * 8) * 2);

    // prologue: issue tile 0
    {
#pragma unroll
        for (int a = 0; a < 4; a++) {
            cpa16(sp + a * AARR,      gp[a]);
            cpa16(sp + a * AARR + 16, gp[a] + 8);
        }
        cp_commit();
    }

    // Q fragments (loaded once; pre-scaled by QSCALE)
    const int r0 = q0 + w * 16 + g;
    uint32_t qfh[4][4], qfl[4][4];
#pragma unroll
    for (int kf = 0; kf < 4; kf++) {
        size_t i0 = base + (size_t)r0 * HDIM + kf * 16 + 2 * tg;
        size_t i1 = base + (size_t)(r0 + 8) * HDIM + kf * 16 + 2 * tg;
        qfh[kf][0] = *(const uint32_t*)&qh_[i0];
        qfh[kf][1] = *(const uint32_t*)&qh_[i1];
        qfh[kf][2] = *(const uint32_t*)&qh_[i0 + 8];
        qfh[kf][3] = *(const uint32_t*)&qh_[i1 + 8];
        qfl[kf][0] = *(const uint32_t*)&ql_[i0];
        qfl[kf][1] = *(const uint32_t*)&ql_[i1];
        qfl[kf][2] = *(const uint32_t*)&ql_[i0 + 8];
        qfl[kf][3] = *(const uint32_t*)&ql_[i1 + 8];
    }

    float o[8][4];
#pragma unroll
    for (int nf = 0; nf < 8; nf++)
#pragma unroll
        for (int e = 0; e < 4; e++) o[nf][e] = 0.f;
    float m1 = -INFINITY, m2 = -INFINITY, l1 = 0.f, l2 = 0.f;

    const int NIT = SEQ / 64;

    for (int it = 0; it < NIT; it++) {
        const int st = it & 1;
        cp_wait0();
        __syncthreads();
        if (it + 1 < NIT) {
            const int k0n = (it + 1) * 64;
            uint32_t dstb = sp + (st ^ 1) * ASTAGE;
            cpa16(dstb,               gp[0] + (size_t)k0n * HDIM);
            cpa16(dstb + 16,          gp[0] + (size_t)k0n * HDIM + 8);
            cpa16(dstb + AARR,        gp[1] + (size_t)k0n * HDIM);
            cpa16(dstb + AARR + 16,   gp[1] + (size_t)k0n * HDIM + 8);
            cpa16(dstb + 2*AARR,      gp[2] + k0n);
            cpa16(dstb + 2*AARR + 16, gp[2] + k0n + 8);
            cpa16(dstb + 3*AARR,      gp[3] + k0n);
            cpa16(dstb + 3*AARR + 16, gp[3] + k0n + 8);
            cp_commit();
        }

        const uint32_t stB = st * ASTAGE;
        const int k0 = it * 64;

        // ----- S = Q @ K^T (bf16x3), exp2 domain -----
        float s[8][4];
#pragma unroll
        for (int nf = 0; nf < 8; nf++)
#pragma unroll
            for (int e = 0; e < 4; e++) s[nf][e] = 0.f;

#pragma unroll
        for (int kf = 0; kf < 4; kf++) {
            uint32_t kh4[4][4], kl4[4][4];
#pragma unroll
            for (int np = 0; np < 4; np++) {
                uint32_t ad = foff + stB + (np * 16 * KSTR + kf * 16) * 2;
                ldsm4(kh4[np], ad);
                ldsm4(kl4[np], ad + AARR);
            }
#pragma unroll
            for (int nf = 0; nf < 8; nf++)
                mma16816(s[nf], qfh[kf], &kh4[nf >> 1][(nf & 1) * 2]);
#pragma unroll
            for (int nf = 0; nf < 8; nf++)
                mma16816(s[nf], qfh[kf], &kl4[nf >> 1][(nf & 1) * 2]);
#pragma unroll
            for (int nf = 0; nf < 8; nf++)
                mma16816(s[nf], qfl[kf], &kh4[nf >> 1][(nf & 1) * 2]);
        }

        // ----- mask (block-skip fast path) -----
        const int mflag = g_mflag[(q0 >> 7) * (SEQ/64) + (k0 >> 6)];
        if (mflag) {
#pragma unroll
            for (int nf = 0; nf < 8; nf++) {
                int kc = k0 + nf * 8 + 2 * tg;
                int2 mv0 = *(const int2*)&mask[(size_t)r0 * SEQ + kc];
                int2 mv1 = *(const int2*)&mask[(size_t)(r0 + 8) * SEQ + kc];
                if (!mv0.x) s[nf][0] = -1e9f;
                if (!mv0.y) s[nf][1] = -1e9f;
                if (!mv1.x) s[nf][2] = -1e9f;
                if (!mv1.y) s[nf][3] = -1e9f;
            }
        }

        // ----- row max + rescale factors -----
        float mt1 = -INFINITY, mt2 = -INFINITY;
#pragma unroll
        for (int nf = 0; nf < 8; nf++) {
            mt1 = fmaxf(mt1, fmaxf(s[nf][0], s[nf][1]));
            mt2 = fmaxf(mt2, fmaxf(s[nf][2], s[nf][3]));
        }
        mt1 = fmaxf(mt1, __shfl_xor_sync(0xffffffffu, mt1, 1));
        mt1 = fmaxf(mt1, __shfl_xor_sync(0xffffffffu, mt1, 2));
        mt2 = fmaxf(mt2, __shfl_xor_sync(0xffffffffu, mt2, 1));
        mt2 = fmaxf(mt2, __shfl_xor_sync(0xffffffffu, mt2, 2));
        float m1n = fmaxf(m1, mt1), m2n = fmaxf(m2, mt2);
        float a1 = ex2(m1 - m1n), a2 = ex2(m2 - m2n);

        // rescale O before accumulating this tile
#pragma unroll
        for (int nf = 0; nf < 8; nf++) {
            o[nf][0] *= a1; o[nf][1] *= a1;
            o[nf][2] *= a2; o[nf][3] *= a2;
        }

        // ----- fused ex2 + pack + PV per key-block (kf) -----
        float sum1 = 0.f, sum2 = 0.f;
#pragma unroll
        for (int kf = 0; kf < 4; kf++) {
            float e00 = ex2(s[2*kf][0]   - m1n), e01 = ex2(s[2*kf][1]   - m1n);
            float e02 = ex2(s[2*kf][2]   - m2n), e03 = ex2(s[2*kf][3]   - m2n);
            float e10 = ex2(s[2*kf+1][0] - m1n), e11 = ex2(s[2*kf+1][1] - m1n);
            float e12 = ex2(s[2*kf+1][2] - m2n), e13 = ex2(s[2*kf+1][3] - m2n);
            sum1 += e00 + e01 + e10 + e11;
            sum2 += e02 + e03 + e12 + e13;

            uint32_t pH[4], pL[4];
            split_pack2(e00, e01, pH[0], pL[0]);
            split_pack2(e02, e03, pH[1], pL[1]);
            split_pack2(e10, e11, pH[2], pL[2]);
            split_pack2(e12, e13, pH[3], pL[3]);

            uint32_t vh4[4][4], vl4[4][4];
#pragma unroll
            for (int np = 0; np < 4; np++) {
                uint32_t ad = foff + stB + 2*AARR + (np * 16 * KSTR + kf * 16) * 2;
                ldsm4(vh4[np], ad);
                ldsm4(vl4[np], ad + AARR);
            }
#pragma unroll
            for (int nf = 0; nf < 8; nf++)
                mma16816(o[nf], pH, &vh4[nf >> 1][(nf & 1) * 2]);
#pragma unroll
            for (int nf = 0; nf < 8; nf++)
                mma16816(o[nf], pH, &vl4[nf >> 1][(nf & 1) * 2]);
#pragma unroll
            for (int nf = 0; nf < 8; nf++)
                mma16816(o[nf], pL, &vh4[nf >> 1][(nf & 1) * 2]);
        }

        // ----- l reduction (overlaps next tile's cp.async wait) -----
        sum1 += __shfl_xor_sync(0xffffffffu, sum1, 1);
        sum1 += __shfl_xor_sync(0xffffffffu, sum1, 2);
        sum2 += __shfl_xor_sync(0xffffffffu, sum2, 1);
        sum2 += __shfl_xor_sync(0xffffffffu, sum2, 2);
        l1 = l1 * a1 + sum1;
        l2 = l2 * a2 + sum2;
        m1 = m1n; m2 = m2n;
    }

    // ----- epilogue: fp32 out [b][s][D] (vectorized, no converts) -----
    const float inv1 = 1.f / l1, inv2 = 1.f / l2;
    const int b = bh / HEADS, h = bh % HEADS;
#pragma unroll
    for (int nf = 0; nf < 8; nf++) {
        int col = h * HDIM + nf * 8 + 2 * tg;
        size_t i0 = ((size_t)(b * SEQ + r0)) * EMBED + col;
        size_t i1 = ((size_t)(b * SEQ + r0 + 8)) * EMBED + col;
        *(float2*)&outF[i0] = make_float2(o[nf][0] * inv1, o[nf][1] * inv1);
        *(float2*)&outF[i1] = make_float2(o[nf][2] * inv2, o[nf][3] * inv2);
    }
}

// ---------------------------------------------------------------------------
extern "C" void kernel_launch(void* const* d_in, const int* in_sizes, int n_in,
                              void* d_out, int out_size)
{
    const float* hidden = (const float*)d_in[0];
    const int*   mask   = (const int*)  d_in[1];
    const float* Wq     = (const float*)d_in[2];
    const float* bq     = (const float*)d_in[3];
    const float* Wk     = (const float*)d_in[4];
    const float* bk     = (const float*)d_in[5];
    const float* Wv     = (const float*)d_in[6];
    const float* bv     = (const float*)d_in[7];
    const float* Wo     = (const float*)d_in[8];
    const float* bo     = (const float*)d_in[9];
    float* out = (float*)d_out;

    __nv_bfloat16 *hh, *hl, *qh, *ql, *kh, *kl, *vth, *vtl;
    float* attnf;
    cudaGetSymbolAddress((void**)&hh,    g_hh);  cudaGetSymbolAddress((void**)&hl,  g_hl);
    cudaGetSymbolAddress((void**)&qh,    g_qh);  cudaGetSymbolAddress((void**)&ql,  g_ql);
    cudaGetSymbolAddress((void**)&kh,    g_kh);  cudaGetSymbolAddress((void**)&kl,  g_kl);
    cudaGetSymbolAddress((void**)&vth,   g_vth); cudaGetSymbolAddress((void**)&vtl, g_vtl);
    cudaGetSymbolAddress((void**)&attnf, g_attnf);

    static bool attr_set = false;
    if (!attr_set) {
        cudaFuncSetAttribute(qkv_kernel,   cudaFuncAttributeMaxDynamicSharedMemorySize, GSMEM);
        cudaFuncSetAttribute(oproj_kernel, cudaFuncAttributeMaxDynamicSharedMemorySize, GSMEM);
        cudaFuncSetAttribute(attn_mma,     cudaFuncAttributeMaxDynamicSharedMemorySize, ASMEM);
        attr_set = true;
    }

    // Fused splits + mask flags
    const size_t nTot = (size_t)NH + 4 * (size_t)NW;   // 8388608
    split_all_kernel<<<(unsigned)(nTot / 8 / 256), 256>>>(hidden, Wq, Wk, Wv, Wo);
    mask_flags_kernel<<<dim3(SEQ/64, SEQ/128), 256>>>(mask);

    // Fused QKV projections (grid.z = 3)
    dim3 gq(EMBED / 128, MTOT / 128, 3);   // (8, 32, 3) = 768 CTAs
    qkv_kernel<<<gq, 256, GSMEM>>>(hh, hl, bq, bk, bv);

    // Attention: fp32 out
    dim3 ag(SEQ / 128, BH);                // (16, 32)
    attn_mma<<<ag, 256, ASMEM>>>(qh, ql, kh, kl, vth, vtl, mask, attnf);

    // Split attention output for O projection, then O projection
    split_attn_kernel<<<NH / 8 / 256, 256>>>();
    dim3 go(EMBED / 128, MTOT / 128);      // (8, 32)
    oproj_kernel<<<go, 256, GSMEM>>>(bo, out);
}